// round 12
// baseline (speedup 1.0000x reference)
#include <cuda_runtime.h>

// ---------------------------------------------------------------------------
// GCN, 3 layers, A = D^-1/2 (Adj+I) D^-1/2.  (R9 config = best known)
// Pull aggregation over per-call CSR; dinv scales fused into GEMM epilogues /
// gathers. GEMMs: tf32 mma.sync.m16n8k8 (fp32 accum). Layer-2 hop streams
// bf16 features.
// THIS ROUND: a diagnostic duplicate GEMM2 launch sits at position 3 so the
// fixed ncu capture (4th launch) profiles the dominant GEMM. Its output is
// overwritten by the real GEMM2 before use — no effect on results.
// ---------------------------------------------------------------------------

#define NODES 100000
#define EDGES 1600000
#define SCAN_BS 1024

__device__ __align__(16) int      g_cnt   [NODES];
__device__ __align__(16) int      g_rowptr[NODES + 1];
__device__ __align__(16) int      g_cursor[NODES];
__device__ __align__(16) int      g_blocksum[(NODES + SCAN_BS - 1) / SCAN_BS + 1];
__device__ __align__(16) float    g_dinv  [NODES];
__device__ __align__(16) int      g_col   [EDGES];
__device__ __align__(16) float    g_buf1[(size_t)NODES * 128];
__device__ __align__(16) float    g_buf2[(size_t)NODES * 128];
__device__ __align__(16) unsigned g_bh [(size_t)NODES * 64];   // bf16 features

template <int SEL>
__device__ __forceinline__ const float* cbuf(const float* ext) {
    if constexpr (SEL == 1) return g_buf1;
    else if constexpr (SEL == 2) return g_buf2;
    else return ext;
}
template <int SEL>
__device__ __forceinline__ float* mbuf(float* ext) {
    if constexpr (SEL == 1) return g_buf1;
    else if constexpr (SEL == 2) return g_buf2;
    else return ext;
}

__device__ __forceinline__ unsigned f2tf32(float f) {
    unsigned r;
    asm("cvt.rna.tf32.f32 %0, %1;" : "=r"(r) : "f"(f));
    return r;
}
__device__ __forceinline__ unsigned pack_bf2(float lo, float hi) {
    unsigned r;
    asm("cvt.rn.bf16x2.f32 %0, %1, %2;" : "=r"(r) : "f"(hi), "f"(lo));
    return r;
}
__device__ __forceinline__ float bf_lo(unsigned u) { return __uint_as_float(u << 16); }
__device__ __forceinline__ float bf_hi(unsigned u) { return __uint_as_float(u & 0xffff0000u); }

// --------------------------- CSR construction ------------------------------
__global__ void cnt_zero_kernel(int n) {
    int i = blockIdx.x * blockDim.x + threadIdx.x;
    if (i < n) g_cnt[i] = 0;
}

__global__ void cnt_count_kernel(const int* __restrict__ ei, int e) {
    int i = blockIdx.x * blockDim.x + threadIdx.x;
    if (i < e) atomicAdd(&g_cnt[ei[e + i]], 1);
}

__global__ void scan1_kernel(int n) {
    __shared__ int sh[SCAN_BS];
    int i = blockIdx.x * SCAN_BS + threadIdx.x;
    int v = (i < n) ? g_cnt[i] : 0;
    if (i < n) g_dinv[i] = rsqrtf((float)(v + 1));   // +1 self-loop
    sh[threadIdx.x] = v;
    __syncthreads();
#pragma unroll
    for (int off = 1; off < SCAN_BS; off <<= 1) {
        int t = (threadIdx.x >= off) ? sh[threadIdx.x - off] : 0;
        __syncthreads();
        sh[threadIdx.x] += t;
        __syncthreads();
    }
    if (i < n) g_rowptr[i + 1] = sh[threadIdx.x];
    if (threadIdx.x == SCAN_BS - 1) g_blocksum[blockIdx.x] = sh[threadIdx.x];
}

// Finalize rowptr + init cursors; per-block blocksum prefix (no serial pass).
__global__ void scan3_kernel(int n) {
    __shared__ int sh_pre;
    int need = (blockIdx.x * 256) / SCAN_BS;
    if (threadIdx.x < 32) {
        int s = 0;
        for (int b = threadIdx.x; b < need; b += 32) s += g_blocksum[b];
#pragma unroll
        for (int o = 16; o; o >>= 1) s += __shfl_down_sync(0xffffffffu, s, o);
        if (threadIdx.x == 0) sh_pre = s;
    }
    __syncthreads();
    int pre = sh_pre;
    int i = blockIdx.x * blockDim.x + threadIdx.x;
    if (i < n) {
        int v = g_rowptr[i + 1] + pre;
        g_rowptr[i + 1] = v;
        if (i + 1 < n) g_cursor[i + 1] = v;
    }
    if (i == 0) { g_rowptr[0] = 0; g_cursor[0] = 0; }
}

__global__ void csr_fill_kernel(const int* __restrict__ ei, int e) {
    int i = blockIdx.x * blockDim.x + threadIdx.x;
    if (i < e) {
        int s = ei[i];
        int d = ei[e + i];
        int pos = atomicAdd(&g_cursor[d], 1);
        g_col[pos] = s;
    }
}

// --------------------------- feature kernels -------------------------------
__global__ void scale_x_kernel(const float* __restrict__ x, int n) {
    int t = blockIdx.x * blockDim.x + threadIdx.x;
    if (t >= n * 16) return;
    int i = t / 16, q = t % 16;
    float dv = g_dinv[i];
    float4 v = *(const float4*)(x + (size_t)i * 64 + q * 4);
    v.x *= dv; v.y *= dv; v.z *= dv; v.w *= dv;
    *(float4*)(g_buf1 + (size_t)i * 64 + q * 4) = v;
}

// fp32 gather (F=64): out[i,:] = dinv[i]*(sum hs[col]+hs[i]) (+bias)
template <int HSEL, int OSEL, bool BIAS>
__global__ void gather64_kernel(const float* h_ext, float* out_ext,
                                const float* __restrict__ bias, int n) {
    const float* __restrict__ hs = cbuf<HSEL>(h_ext);
    float* __restrict__ out = mbuf<OSEL>(out_ext);
    int warp = (blockIdx.x * blockDim.x + threadIdx.x) >> 5;
    int lane = threadIdx.x & 31;
    if (warp >= n) return;
    int beg = g_rowptr[warp], end = g_rowptr[warp + 1];

    float2 acc = *(const float2*)(hs + (size_t)warp * 64 + lane * 2);
    for (int base = beg; base < end; base += 32) {
        int e = base + lane;
        int c = (e < end) ? g_col[e] : 0;
        int m = min(32, end - base);
        for (int j = 0; j < m; j++) {
            int s = __shfl_sync(0xffffffffu, c, j);
            float2 v = *(const float2*)(hs + (size_t)s * 64 + lane * 2);
            acc.x += v.x; acc.y += v.y;
        }
    }
    float dv = g_dinv[warp];
    acc.x *= dv; acc.y *= dv;
    if constexpr (BIAS) { acc.x += bias[lane * 2]; acc.y += bias[lane * 2 + 1]; }
    *(float2*)(out + (size_t)warp * 64 + lane * 2) = acc;
}

// Layer-2 gather: bf16 features in (g_bh), fp32 out (buf1).
__global__ void gather2bf_kernel(int n) {
    int warp = (blockIdx.x * blockDim.x + threadIdx.x) >> 5;
    int lane = threadIdx.x & 31;
    if (warp >= n) return;
    int beg = g_rowptr[warp], end = g_rowptr[warp + 1];

    uint2 sv = *(const uint2*)(g_bh + (size_t)warp * 64 + lane * 2);
    float4 acc = make_float4(bf_lo(sv.x), bf_hi(sv.x), bf_lo(sv.y), bf_hi(sv.y));
    for (int base = beg; base < end; base += 32) {
        int e = base + lane;
        int c = (e < end) ? g_col[e] : 0;
        int m = min(32, end - base);
        for (int j = 0; j < m; j++) {
            int s = __shfl_sync(0xffffffffu, c, j);
            uint2 v = *(const uint2*)(g_bh + (size_t)s * 64 + lane * 2);
            acc.x += bf_lo(v.x); acc.y += bf_hi(v.x);
            acc.z += bf_lo(v.y); acc.w += bf_hi(v.y);
        }
    }
    float dv = g_dinv[warp];
    acc.x *= dv; acc.y *= dv; acc.z *= dv; acc.w *= dv;
    *(float4*)(g_buf1 + (size_t)warp * 128 + lane * 4) = acc;
}

// ---------------------------------------------------------------------------
// TF32 tensor-core GEMM: C = A @ W (+bias)(+relu)(*dinv[row]).
// Block tile 128x64, 256 threads (8 warps, 4x2), warp tile 32x32
// (2x4 m16n8k8 atoms), BK=32 staged in padded smem.
// OUTBF: pack output pairs to bf16x2 into g_bh instead of fp32 C.
// ---------------------------------------------------------------------------
template <int K, int NOUT, bool RELU, bool BIAS, bool SCALE, int ASEL, int CSEL, bool OUTBF>
__global__ void gemm_tf32_kernel(const float* A_ext,
                                 const float* __restrict__ W,
                                 const float* __restrict__ bias,
                                 float* C_ext, int n) {
    const float* __restrict__ A = cbuf<ASEL>(A_ext);
    float* __restrict__ C = mbuf<CSEL>(C_ext);

    __shared__ unsigned As[32][132];
    __shared__ unsigned Bs[32][68];

    const int tid = threadIdx.x;
    const int wid = tid >> 5;
    const int lane = tid & 31;
    const int warp_m = wid & 3;
    const int warp_n = wid >> 2;
    const int lk = lane & 3;
    const int lg = lane >> 2;
    const int rowBase = blockIdx.y * 128;
    const int colBase = blockIdx.x * 64;

    float acc[2][4][4];
#pragma unroll
    for (int mi = 0; mi < 2; mi++)
#pragma unroll
        for (int ni = 0; ni < 4; ni++)
#pragma unroll
            for (int r = 0; r < 4; r++) acc[mi][ni][r] = 0.0f;

    for (int ks = 0; ks < K; ks += 32) {
#pragma unroll
        for (int l = 0; l < 4; l++) {
            int f = tid + l * 256;
            int row = f >> 3;
            int kq = f & 7;
            int rg = rowBase + row;
            float4 v = make_float4(0.f, 0.f, 0.f, 0.f);
            if (rg < n) v = *(const float4*)(A + (size_t)rg * K + ks + kq * 4);
            As[kq * 4 + 0][row] = f2tf32(v.x);
            As[kq * 4 + 1][row] = f2tf32(v.y);
            As[kq * 4 + 2][row] = f2tf32(v.z);
            As[kq * 4 + 3][row] = f2tf32(v.w);
        }
#pragma unroll
        for (int l = 0; l < 2; l++) {
            int f = tid + l * 256;
            int k = f >> 4;
            int cq = f & 15;
            float4 v = *(const float4*)(W + (size_t)(ks + k) * NOUT + colBase + cq * 4);
            Bs[k][cq * 4 + 0] = f2tf32(v.x);
            Bs[k][cq * 4 + 1] = f2tf32(v.y);
            Bs[k][cq * 4 + 2] = f2tf32(v.z);
            Bs[k][cq * 4 + 3] = f2tf32(v.w);
        }
        __syncthreads();

#pragma unroll
        for (int ka = 0; ka < 4; ka++) {
            const int kb = ka * 8;
            unsigned a[2][4], b[4][2];
#pragma unroll
            for (int mi = 0; mi < 2; mi++) {
                int m0 = warp_m * 32 + mi * 16;
                a[mi][0] = As[kb + lk    ][m0 + lg    ];
                a[mi][1] = As[kb + lk    ][m0 + lg + 8];
                a[mi][2] = As[kb + lk + 4][m0 + lg    ];
                a[mi][3] = As[kb + lk + 4][m0 + lg + 8];
            }
#pragma unroll
            for (int ni = 0; ni < 4; ni++) {
                int n0 = warp_n * 32 + ni * 8;
                b[ni][0] = Bs[kb + lk    ][n0 + lg];
                b[ni][1] = Bs[kb + lk + 4][n0 + lg];
            }
#pragma unroll
            for (int mi = 0; mi < 2; mi++)
#pragma unroll
                for (int ni = 0; ni < 4; ni++) {
                    asm volatile(
                        "mma.sync.aligned.m16n8k8.row.col.f32.tf32.tf32.f32 "
                        "{%0,%1,%2,%3}, {%4,%5,%6,%7}, {%8,%9}, {%0,%1,%2,%3};"
                        : "+f"(acc[mi][ni][0]), "+f"(acc[mi][ni][1]),
                          "+f"(acc[mi][ni][2]), "+f"(acc[mi][ni][3])
                        : "r"(a[mi][0]), "r"(a[mi][1]), "r"(a[mi][2]), "r"(a[mi][3]),
                          "r"(b[ni][0]), "r"(b[ni][1]));
                }
        }
        __syncthreads();
    }

#pragma unroll
    for (int mi = 0; mi < 2; mi++) {
        int row0 = rowBase + warp_m * 32 + mi * 16 + lg;
        int row1 = row0 + 8;
        float dv0 = 1.0f, dv1 = 1.0f;
        if (SCALE) {
            if (row0 < n) dv0 = g_dinv[row0];
            if (row1 < n) dv1 = g_dinv[row1];
        }
#pragma unroll
        for (int ni = 0; ni < 4; ni++) {
            int col = colBase + warp_n * 32 + ni * 8 + lk * 2;
            float bx = 0.f, by = 0.f;
            if (BIAS) { bx = bias[col]; by = bias[col + 1]; }
            float v0 = acc[mi][ni][0] + bx;
            float v1 = acc[mi][ni][1] + by;
            float v2 = acc[mi][ni][2] + bx;
            float v3 = acc[mi][ni][3] + by;
            if (RELU) {
                v0 = fmaxf(v0, 0.f); v1 = fmaxf(v1, 0.f);
                v2 = fmaxf(v2, 0.f); v3 = fmaxf(v3, 0.f);
            }
            if constexpr (OUTBF) {
                if (row0 < n) g_bh[(size_t)row0 * (NOUT / 2) + (col >> 1)] = pack_bf2(v0 * dv0, v1 * dv0);
                if (row1 < n) g_bh[(size_t)row1 * (NOUT / 2) + (col >> 1)] = pack_bf2(v2 * dv1, v3 * dv1);
            } else {
                if (row0 < n) *(float2*)(C + (size_t)row0 * NOUT + col) = make_float2(v0 * dv0, v1 * dv0);
                if (row1 < n) *(float2*)(C + (size_t)row1 * NOUT + col) = make_float2(v2 * dv1, v3 * dv1);
            }
        }
    }
}

// ---------------------------------------------------------------------------
extern "C" void kernel_launch(void* const* d_in, const int* in_sizes, int n_in,
                              void* d_out, int out_size) {
    const float* x   = (const float*)d_in[0];
    const int*   ei  = (const int*)d_in[1];
    const float* W1  = (const float*)d_in[2];
    const float* b1  = (const float*)d_in[3];
    const float* W2  = (const float*)d_in[4];
    const float* b2  = (const float*)d_in[5];
    const float* W3  = (const float*)d_in[6];
    const float* b3  = (const float*)d_in[7];
    float* out = (float*)d_out;

    const int N = in_sizes[0] / 64;
    const int E = in_sizes[1] / 2;
    const int NB = (N + SCAN_BS - 1) / SCAN_BS;

    const int T = 256;
    auto blk = [&](long long w) { return (int)((w + T - 1) / T); };

    const int GT = 256;
    const int gblk = (N + 7) / 8;
    const int gy = (N + 127) / 128;

    // ---- CSR build + norms ----
    cnt_zero_kernel<<<blk(N), T>>>(N);                 // launch 0
    cnt_count_kernel<<<blk(E), T>>>(ei, E);            // launch 1
    scan1_kernel<<<NB, SCAN_BS>>>(N);                  // launch 2

    // DIAGNOSTIC (launch 3 — the one ncu captures): duplicate of GEMM2 on
    // stale-but-valid buffers; its buf2 output is fully overwritten by the
    // real GEMM2 below before any consumer reads it.
    gemm_tf32_kernel<128, 128, true, true, true, 1, 2, false><<<dim3(2, gy), 256>>>(nullptr, W2, b2, nullptr, N);

    scan3_kernel<<<blk(N), T>>>(N);                    // launch 4
    csr_fill_kernel<<<blk(E), T>>>(ei, E);             // launch 5

    // ---- Layer 1: xs = x*dinv (buf1); g1 = dinv*gather(xs) (buf2);
    //      h1bf = bf16(relu(g1 W1 + b1)*dinv) (g_bh)
    scale_x_kernel<<<blk((long long)N * 16), T>>>(x, N);
    gather64_kernel<1, 2, false><<<gblk, GT>>>(nullptr, nullptr, nullptr, N);
    gemm_tf32_kernel<64, 128, true, true, true, 2, 0, true><<<dim3(2, gy), 256>>>(nullptr, W1, b1, nullptr, N);

    // ---- Layer 2: g2 = dinv*gather(h1bf) (buf1); h2s = relu(g2 W2 + b2)*dinv (buf2)
    gather2bf_kernel<<<gblk, GT>>>(N);
    gemm_tf32_kernel<128, 128, true, true, true, 1, 2, false><<<dim3(2, gy), 256>>>(nullptr, W2, b2, nullptr, N);

    // ---- Layer 3: ps = h2s W3 (buf1); out = dinv*gather(ps) + b3
    gemm_tf32_kernel<128, 64, false, false, false, 2, 1, false><<<dim3(1, gy), 256>>>(nullptr, W3, nullptr, nullptr, N);
    gather64_kernel<1, 0, true><<<gblk, GT>>>(nullptr, out, b3, N);
}

// round 13
// speedup vs baseline: 1.3221x; 1.3221x over previous
#include <cuda_runtime.h>

// ---------------------------------------------------------------------------
// GCN, 3 layers, A = D^-1/2 (Adj+I) D^-1/2.
// Pull aggregation over per-call CSR; dinv scales fused into GEMM epilogues /
// gathers. GEMMs: tf32 mma.sync.m16n8k8 (fp32 accum), layer-2 hop streams
// bf16 features.
// R13: GEMM smem revamp — A stays row-major ([m][k], pad 36) so staging is
// STS.128 (was 16x STS.32 transpose); B pad 72; both fragment-load patterns
// are exactly conflict-free. Cuts smem instruction count ~3.2x (GEMM was
// L1/LSU-bound at 73.6% with tensor at 17.8%).
// ---------------------------------------------------------------------------

#define NODES 100000
#define EDGES 1600000
#define SCAN_BS 1024

__device__ __align__(16) int      g_cnt   [NODES];
__device__ __align__(16) int      g_rowptr[NODES + 1];
__device__ __align__(16) int      g_cursor[NODES];
__device__ __align__(16) int      g_blocksum[(NODES + SCAN_BS - 1) / SCAN_BS + 1];
__device__ __align__(16) float    g_dinv  [NODES];
__device__ __align__(16) int      g_col   [EDGES];
__device__ __align__(16) float    g_buf1[(size_t)NODES * 128];
__device__ __align__(16) float    g_buf2[(size_t)NODES * 128];
__device__ __align__(16) unsigned g_bh [(size_t)NODES * 64];   // bf16 features

template <int SEL>
__device__ __forceinline__ const float* cbuf(const float* ext) {
    if constexpr (SEL == 1) return g_buf1;
    else if constexpr (SEL == 2) return g_buf2;
    else return ext;
}
template <int SEL>
__device__ __forceinline__ float* mbuf(float* ext) {
    if constexpr (SEL == 1) return g_buf1;
    else if constexpr (SEL == 2) return g_buf2;
    else return ext;
}

__device__ __forceinline__ unsigned f2tf32(float f) {
    unsigned r;
    asm("cvt.rna.tf32.f32 %0, %1;" : "=r"(r) : "f"(f));
    return r;
}
__device__ __forceinline__ unsigned pack_bf2(float lo, float hi) {
    unsigned r;
    asm("cvt.rn.bf16x2.f32 %0, %1, %2;" : "=r"(r) : "f"(hi), "f"(lo));
    return r;
}
__device__ __forceinline__ float bf_lo(unsigned u) { return __uint_as_float(u << 16); }
__device__ __forceinline__ float bf_hi(unsigned u) { return __uint_as_float(u & 0xffff0000u); }

// --------------------------- CSR construction ------------------------------
__global__ void cnt_zero_kernel(int n) {
    int i = blockIdx.x * blockDim.x + threadIdx.x;
    if (i < n) g_cnt[i] = 0;
}

__global__ void cnt_count_kernel(const int* __restrict__ ei, int e) {
    int i = blockIdx.x * blockDim.x + threadIdx.x;
    if (i < e) atomicAdd(&g_cnt[ei[e + i]], 1);
}

__global__ void scan1_kernel(int n) {
    __shared__ int sh[SCAN_BS];
    int i = blockIdx.x * SCAN_BS + threadIdx.x;
    int v = (i < n) ? g_cnt[i] : 0;
    if (i < n) g_dinv[i] = rsqrtf((float)(v + 1));   // +1 self-loop
    sh[threadIdx.x] = v;
    __syncthreads();
#pragma unroll
    for (int off = 1; off < SCAN_BS; off <<= 1) {
        int t = (threadIdx.x >= off) ? sh[threadIdx.x - off] : 0;
        __syncthreads();
        sh[threadIdx.x] += t;
        __syncthreads();
    }
    if (i < n) g_rowptr[i + 1] = sh[threadIdx.x];
    if (threadIdx.x == SCAN_BS - 1) g_blocksum[blockIdx.x] = sh[threadIdx.x];
}

// Finalize rowptr + init cursors; per-block blocksum prefix (no serial pass).
__global__ void scan3_kernel(int n) {
    __shared__ int sh_pre;
    int need = (blockIdx.x * 256) / SCAN_BS;
    if (threadIdx.x < 32) {
        int s = 0;
        for (int b = threadIdx.x; b < need; b += 32) s += g_blocksum[b];
#pragma unroll
        for (int o = 16; o; o >>= 1) s += __shfl_down_sync(0xffffffffu, s, o);
        if (threadIdx.x == 0) sh_pre = s;
    }
    __syncthreads();
    int pre = sh_pre;
    int i = blockIdx.x * blockDim.x + threadIdx.x;
    if (i < n) {
        int v = g_rowptr[i + 1] + pre;
        g_rowptr[i + 1] = v;
        if (i + 1 < n) g_cursor[i + 1] = v;
    }
    if (i == 0) { g_rowptr[0] = 0; g_cursor[0] = 0; }
}

__global__ void csr_fill_kernel(const int* __restrict__ ei, int e) {
    int i = blockIdx.x * blockDim.x + threadIdx.x;
    if (i < e) {
        int s = ei[i];
        int d = ei[e + i];
        int pos = atomicAdd(&g_cursor[d], 1);
        g_col[pos] = s;
    }
}

// --------------------------- feature kernels -------------------------------
__global__ void scale_x_kernel(const float* __restrict__ x, int n) {
    int t = blockIdx.x * blockDim.x + threadIdx.x;
    if (t >= n * 16) return;
    int i = t / 16, q = t % 16;
    float dv = g_dinv[i];
    float4 v = *(const float4*)(x + (size_t)i * 64 + q * 4);
    v.x *= dv; v.y *= dv; v.z *= dv; v.w *= dv;
    *(float4*)(g_buf1 + (size_t)i * 64 + q * 4) = v;
}

// fp32 gather (F=64): out[i,:] = dinv[i]*(sum hs[col]+hs[i]) (+bias)
template <int HSEL, int OSEL, bool BIAS>
__global__ void gather64_kernel(const float* h_ext, float* out_ext,
                                const float* __restrict__ bias, int n) {
    const float* __restrict__ hs = cbuf<HSEL>(h_ext);
    float* __restrict__ out = mbuf<OSEL>(out_ext);
    int warp = (blockIdx.x * blockDim.x + threadIdx.x) >> 5;
    int lane = threadIdx.x & 31;
    if (warp >= n) return;
    int beg = g_rowptr[warp], end = g_rowptr[warp + 1];

    float2 acc = *(const float2*)(hs + (size_t)warp * 64 + lane * 2);
    for (int base = beg; base < end; base += 32) {
        int e = base + lane;
        int c = (e < end) ? g_col[e] : 0;
        int m = min(32, end - base);
        for (int j = 0; j < m; j++) {
            int s = __shfl_sync(0xffffffffu, c, j);
            float2 v = *(const float2*)(hs + (size_t)s * 64 + lane * 2);
            acc.x += v.x; acc.y += v.y;
        }
    }
    float dv = g_dinv[warp];
    acc.x *= dv; acc.y *= dv;
    if constexpr (BIAS) { acc.x += bias[lane * 2]; acc.y += bias[lane * 2 + 1]; }
    *(float2*)(out + (size_t)warp * 64 + lane * 2) = acc;
}

// Layer-2 gather: bf16 features in (g_bh), fp32 out (buf1).
__global__ void gather2bf_kernel(int n) {
    int warp = (blockIdx.x * blockDim.x + threadIdx.x) >> 5;
    int lane = threadIdx.x & 31;
    if (warp >= n) return;
    int beg = g_rowptr[warp], end = g_rowptr[warp + 1];

    uint2 sv = *(const uint2*)(g_bh + (size_t)warp * 64 + lane * 2);
    float4 acc = make_float4(bf_lo(sv.x), bf_hi(sv.x), bf_lo(sv.y), bf_hi(sv.y));
    for (int base = beg; base < end; base += 32) {
        int e = base + lane;
        int c = (e < end) ? g_col[e] : 0;
        int m = min(32, end - base);
        for (int j = 0; j < m; j++) {
            int s = __shfl_sync(0xffffffffu, c, j);
            uint2 v = *(const uint2*)(g_bh + (size_t)s * 64 + lane * 2);
            acc.x += bf_lo(v.x); acc.y += bf_hi(v.x);
            acc.z += bf_lo(v.y); acc.w += bf_hi(v.y);
        }
    }
    float dv = g_dinv[warp];
    acc.x *= dv; acc.y *= dv; acc.z *= dv; acc.w *= dv;
    *(float4*)(g_buf1 + (size_t)warp * 128 + lane * 4) = acc;
}

// ---------------------------------------------------------------------------
// TF32 tensor-core GEMM: C = A @ W (+bias)(+relu)(*dinv[row]).
// Block tile 128x64, 256 threads (8 warps, 4x2), warp tile 32x32
// (2x4 m16n8k8 atoms), BK=32.
// As row-major [m][36]: staging = 1 STS.128 per float4 (no transpose);
// fragment a-load bank = 4*lg+lk (conflict-free).
// Bs [k][72]: staging = 1 STS.128 per float4; b-load bank = 8*lk+lg
// (conflict-free).
// OUTBF: pack output pairs to bf16x2 into g_bh instead of fp32 C.
// ---------------------------------------------------------------------------
template <int K, int NOUT, bool RELU, bool BIAS, bool SCALE, int ASEL, int CSEL, bool OUTBF>
__global__ void gemm_tf32_kernel(const float* A_ext,
                                 const float* __restrict__ W,
                                 const float* __restrict__ bias,
                                 float* C_ext, int n) {
    const float* __restrict__ A = cbuf<ASEL>(A_ext);
    float* __restrict__ C = mbuf<CSEL>(C_ext);

    __shared__ unsigned As[128][36];   // [m][k], pad 36 -> 16B-aligned rows
    __shared__ unsigned Bs[32][72];    // [k][n], pad 72

    const int tid = threadIdx.x;
    const int wid = tid >> 5;
    const int lane = tid & 31;
    const int warp_m = wid & 3;
    const int warp_n = wid >> 2;
    const int lk = lane & 3;
    const int lg = lane >> 2;
    const int rowBase = blockIdx.y * 128;
    const int colBase = blockIdx.x * 64;

    float acc[2][4][4];
#pragma unroll
    for (int mi = 0; mi < 2; mi++)
#pragma unroll
        for (int ni = 0; ni < 4; ni++)
#pragma unroll
            for (int r = 0; r < 4; r++) acc[mi][ni][r] = 0.0f;

    for (int ks = 0; ks < K; ks += 32) {
        // Stage A: 128 rows x 32 k; one vectorized 16B store per float4.
#pragma unroll
        for (int l = 0; l < 4; l++) {
            int f = tid + l * 256;
            int row = f >> 3;
            int kq = f & 7;
            int rg = rowBase + row;
            float4 v = make_float4(0.f, 0.f, 0.f, 0.f);
            if (rg < n) v = *(const float4*)(A + (size_t)rg * K + ks + kq * 4);
            uint4 t;
            t.x = f2tf32(v.x); t.y = f2tf32(v.y);
            t.z = f2tf32(v.z); t.w = f2tf32(v.w);
            *(uint4*)&As[row][kq * 4] = t;
        }
        // Stage B: 32 k x 64 n; one vectorized 16B store per float4.
#pragma unroll
        for (int l = 0; l < 2; l++) {
            int f = tid + l * 256;
            int k = f >> 4;
            int cq = f & 15;
            float4 v = *(const float4*)(W + (size_t)(ks + k) * NOUT + colBase + cq * 4);
            uint4 t;
            t.x = f2tf32(v.x); t.y = f2tf32(v.y);
            t.z = f2tf32(v.z); t.w = f2tf32(v.w);
            *(uint4*)&Bs[k][cq * 4] = t;
        }
        __syncthreads();

#pragma unroll
        for (int ka = 0; ka < 4; ka++) {
            const int kb = ka * 8;
            unsigned a[2][4], b[4][2];
#pragma unroll
            for (int mi = 0; mi < 2; mi++) {
                int m0 = warp_m * 32 + mi * 16;
                a[mi][0] = As[m0 + lg    ][kb + lk    ];
                a[mi][1] = As[m0 + lg + 8][kb + lk    ];
                a[mi][2] = As[m0 + lg    ][kb + lk + 4];
                a[mi][3] = As[m0 + lg + 8][kb + lk + 4];
            }
#pragma unroll
            for (int ni = 0; ni < 4; ni++) {
                int n0 = warp_n * 32 + ni * 8;
                b[ni][0] = Bs[kb + lk    ][n0 + lg];
                b[ni][1] = Bs[kb + lk + 4][n0 + lg];
            }
#pragma unroll
            for (int mi = 0; mi < 2; mi++)
#pragma unroll
                for (int ni = 0; ni < 4; ni++) {
                    asm volatile(
                        "mma.sync.aligned.m16n8k8.row.col.f32.tf32.tf32.f32 "
                        "{%0,%1,%2,%3}, {%4,%5,%6,%7}, {%8,%9}, {%0,%1,%2,%3};"
                        : "+f"(acc[mi][ni][0]), "+f"(acc[mi][ni][1]),
                          "+f"(acc[mi][ni][2]), "+f"(acc[mi][ni][3])
                        : "r"(a[mi][0]), "r"(a[mi][1]), "r"(a[mi][2]), "r"(a[mi][3]),
                          "r"(b[ni][0]), "r"(b[ni][1]));
                }
        }
        __syncthreads();
    }

#pragma unroll
    for (int mi = 0; mi < 2; mi++) {
        int row0 = rowBase + warp_m * 32 + mi * 16 + lg;
        int row1 = row0 + 8;
        float dv0 = 1.0f, dv1 = 1.0f;
        if (SCALE) {
            if (row0 < n) dv0 = g_dinv[row0];
            if (row1 < n) dv1 = g_dinv[row1];
        }
#pragma unroll
        for (int ni = 0; ni < 4; ni++) {
            int col = colBase + warp_n * 32 + ni * 8 + lk * 2;
            float bx = 0.f, by = 0.f;
            if (BIAS) { bx = bias[col]; by = bias[col + 1]; }
            float v0 = acc[mi][ni][0] + bx;
            float v1 = acc[mi][ni][1] + by;
            float v2 = acc[mi][ni][2] + bx;
            float v3 = acc[mi][ni][3] + by;
            if (RELU) {
                v0 = fmaxf(v0, 0.f); v1 = fmaxf(v1, 0.f);
                v2 = fmaxf(v2, 0.f); v3 = fmaxf(v3, 0.f);
            }
            if constexpr (OUTBF) {
                if (row0 < n) g_bh[(size_t)row0 * (NOUT / 2) + (col >> 1)] = pack_bf2(v0 * dv0, v1 * dv0);
                if (row1 < n) g_bh[(size_t)row1 * (NOUT / 2) + (col >> 1)] = pack_bf2(v2 * dv1, v3 * dv1);
            } else {
                if (row0 < n) *(float2*)(C + (size_t)row0 * NOUT + col) = make_float2(v0 * dv0, v1 * dv0);
                if (row1 < n) *(float2*)(C + (size_t)row1 * NOUT + col) = make_float2(v2 * dv1, v3 * dv1);
            }
        }
    }
}

// ---------------------------------------------------------------------------
extern "C" void kernel_launch(void* const* d_in, const int* in_sizes, int n_in,
                              void* d_out, int out_size) {
    const float* x   = (const float*)d_in[0];
    const int*   ei  = (const int*)d_in[1];
    const float* W1  = (const float*)d_in[2];
    const float* b1  = (const float*)d_in[3];
    const float* W2  = (const float*)d_in[4];
    const float* b2  = (const float*)d_in[5];
    const float* W3  = (const float*)d_in[6];
    const float* b3  = (const float*)d_in[7];
    float* out = (float*)d_out;

    const int N = in_sizes[0] / 64;
    const int E = in_sizes[1] / 2;
    const int NB = (N + SCAN_BS - 1) / SCAN_BS;

    const int T = 256;
    auto blk = [&](long long w) { return (int)((w + T - 1) / T); };

    // ---- CSR build + norms ----
    cnt_zero_kernel<<<blk(N), T>>>(N);
    cnt_count_kernel<<<blk(E), T>>>(ei, E);
    scan1_kernel<<<NB, SCAN_BS>>>(N);
    scan3_kernel<<<blk(N), T>>>(N);
    csr_fill_kernel<<<blk(E), T>>>(ei, E);

    const int GT = 256;
    const int gblk = (N + 7) / 8;
    const int gy = (N + 127) / 128;

    // ---- Layer 1: xs = x*dinv (buf1); g1 = dinv*gather(xs) (buf2);
    //      h1bf = bf16(relu(g1 W1 + b1)*dinv) (g_bh)
    scale_x_kernel<<<blk((long long)N * 16), T>>>(x, N);
    gather64_kernel<1, 2, false><<<gblk, GT>>>(nullptr, nullptr, nullptr, N);
    gemm_tf32_kernel<64, 128, true, true, true, 2, 0, true><<<dim3(2, gy), 256>>>(nullptr, W1, b1, nullptr, N);

    // ---- Layer 2: g2 = dinv*gather(h1bf) (buf1); h2s = relu(g2 W2 + b2)*dinv (buf2)
    gather2bf_kernel<<<gblk, GT>>>(N);
    gemm_tf32_kernel<128, 128, true, true, true, 1, 2, false><<<dim3(2, gy), 256>>>(nullptr, W2, b2, nullptr, N);

    // ---- Layer 3: ps = h2s W3 (buf1); out = dinv*gather(ps) + b3
    gemm_tf32_kernel<128, 64, false, false, false, 2, 1, false><<<dim3(1, gy), 256>>>(nullptr, W3, nullptr, nullptr, N);
    gather64_kernel<1, 0, true><<<gblk, GT>>>(nullptr, out, b3, N);
}